// round 5
// baseline (speedup 1.0000x reference)
#include <cuda_runtime.h>
#include <math.h>

#define HW 4096
#define NTILES 640
#define NHALF  1280
#define NTOT_F 2621440.0f
#define EPS_V 1e-8f

#define SPARSITY_W 0.8f
#define CONC_W     1.5f
#define COORD_W    1.0f
#define BG_W       0.1f

__device__ float g_part[NHALF][10];      // per-half-tile partial stats
__device__ float g_tile_contrib[NTILES];
__device__ unsigned int g_tile_cnt[NTILES];  // zero-initialized; reset after use
__device__ unsigned int g_done = 0;

__device__ __forceinline__ float fast_tanh(float x) {
    float r;
    asm("tanh.approx.f32 %0, %1;" : "=f"(r) : "f"(x));
    return r;
}

// One CTA per HALF tile (32 rows): 256 threads, 8 px/thread (2 float4 groups).
__global__ __launch_bounds__(256, 4)
void loss_kernel(const float4* __restrict__ pred,
                 const float4* __restrict__ tgt,
                 float* __restrict__ out) {
    __shared__ float warp_red[8][10];
    __shared__ bool is_last;

    const int hidx = blockIdx.x;          // half index [0,1280)
    const int tile = hidx >> 1;
    const int half = hidx & 1;
    const size_t base = (size_t)tile * (HW / 4) + (size_t)half * 512;

    const int tid  = threadIdx.x;
    const int lane = tid & 31;
    const int wid  = tid >> 5;

    // element j = 4*v, v = tid + 256k (+512*half within tile)
    //   col = ((4*tid)&63) + c   (k,half-invariant)
    //   row = (tid>>4) + 16k + 32*half
    const float c0f = (float)((tid * 4) & 63);
    const float y0f = (float)((tid >> 4) + 32 * half);

    // front-load all 4 vectors (MLP=4)
    const float4* __restrict__ P = pred + base;
    const float4* __restrict__ T = tgt  + base;
    float4 xa = P[tid];        float4 xb = P[tid + 256];
    float4 ta = T[tid];        float4 tb = T[tid + 256];

    float S0 = 0.f, S1 = 0.f, T0 = 0.f, T1 = 0.f;
    float wxp = 0.f, wxt = 0.f;
    float foc = 0.f, bg = 0.f, plog = 0.f, mxh = -0.5f;

    #pragma unroll
    for (int k = 0; k < 2; k++) {
        float xv[4], tv[4];
        if (k == 0) { xv[0]=xa.x; xv[1]=xa.y; xv[2]=xa.z; xv[3]=xa.w;
                      tv[0]=ta.x; tv[1]=ta.y; tv[2]=ta.z; tv[3]=ta.w; }
        else        { xv[0]=xb.x; xv[1]=xb.y; xv[2]=xb.z; xv[3]=xb.w;
                      tv[0]=tb.x; tv[1]=tb.y; tv[2]=tb.z; tv[3]=tb.w; }
        float pv[4];
        #pragma unroll
        for (int c = 0; c < 4; c++) {
            float x = xv[c];
            float t = tv[c];
            float h  = 0.5f * fast_tanh(0.5f * x);   // p - 0.5
            float p  = h + 0.5f;
            pv[c] = p;
            float pm = 0.5f + fabsf(h);              // sigmoid(|x|)
            float lp = __logf(pm);                   // -lp = log1p(e^{-|x|})
            float bce = fmaf(-x, t, fmaxf(x, 0.f) - lp);
            float om  = fabsf(t - p);                // 1 - p_t  (t in {0,1})
            float om2 = om * om;
            foc  = fmaf(om2, bce, foc);
            bg   = fmaf(om2, 1.f - t, bg);           // p^2*(1-t) == om^2*(1-t)
            plog = fmaf(p, fminf(x, 0.f) + lp, plog);
            mxh  = fmaxf(mxh, h);
        }
        float gs = (pv[0] + pv[1]) + (pv[2] + pv[3]);
        float gw = fmaf(3.f, pv[3], fmaf(2.f, pv[2], pv[1]));
        float gt = (tv[0] + tv[1]) + (tv[2] + tv[3]);
        float gu = fmaf(3.f, tv[3], fmaf(2.f, tv[2], tv[1]));
        if (k == 0) { S0 += gs; T0 += gt; } else { S1 += gs; T1 += gt; }
        wxp += gw;  wxt += gu;
    }

    float S  = S0 + S1;
    float Ts = T0 + T1;
    float pxs = fmaf(c0f, S,  wxp);
    float pys = fmaf(y0f, S,  16.f * S1);   // rows: y0 + 16k
    float txs = fmaf(c0f, Ts, wxt);
    float tys = fmaf(y0f, Ts, 16.f * T1);
    float mx  = mxh + 0.5f;

    // warp butterfly reduction: 9 sums + 1 max
    const unsigned FULL = 0xffffffffu;
    #pragma unroll
    for (int o = 16; o; o >>= 1) {
        S    += __shfl_xor_sync(FULL, S,    o);
        Ts   += __shfl_xor_sync(FULL, Ts,   o);
        pxs  += __shfl_xor_sync(FULL, pxs,  o);
        pys  += __shfl_xor_sync(FULL, pys,  o);
        txs  += __shfl_xor_sync(FULL, txs,  o);
        tys  += __shfl_xor_sync(FULL, tys,  o);
        foc  += __shfl_xor_sync(FULL, foc,  o);
        bg   += __shfl_xor_sync(FULL, bg,   o);
        plog += __shfl_xor_sync(FULL, plog, o);
        mx    = fmaxf(mx, __shfl_xor_sync(FULL, mx, o));
    }
    if (lane == 0) {
        warp_red[wid][0] = S;    warp_red[wid][1] = Ts;
        warp_red[wid][2] = pxs;  warp_red[wid][3] = pys;
        warp_red[wid][4] = txs;  warp_red[wid][5] = tys;
        warp_red[wid][6] = foc;  warp_red[wid][7] = bg;
        warp_red[wid][8] = plog; warp_red[wid][9] = mx;
    }
    __syncthreads();

    if (wid == 0 && lane < 8) {
        float a[10];
        #pragma unroll
        for (int i = 0; i < 10; i++) a[i] = warp_red[lane][i];
        const unsigned M8 = 0x000000ffu;
        #pragma unroll
        for (int o = 4; o; o >>= 1) {
            #pragma unroll
            for (int i = 0; i < 9; i++) a[i] += __shfl_xor_sync(M8, a[i], o);
            a[9] = fmaxf(a[9], __shfl_xor_sync(M8, a[9], o));
        }
        if (lane == 0) {
            // publish my half's partials
            #pragma unroll
            for (int i = 0; i < 10; i++) g_part[hidx][i] = a[i];
            __threadfence();
            unsigned r = atomicAdd(&g_tile_cnt[tile], 1u);
            bool second = (r == 1);
            bool last = false;
            if (second) {
                __threadfence();
                // combine with the other half (commutative -> deterministic)
                const int other = hidx ^ 1;
                float b[10];
                #pragma unroll
                for (int i = 0; i < 10; i++) b[i] = g_part[other][i];
                #pragma unroll
                for (int i = 0; i < 9; i++) a[i] += b[i];
                a[9] = fmaxf(a[9], b[9]);

                float Sp  = a[0] + EPS_V;
                float inv = 1.f / Sp;
                float ent = inv * (a[0] * logf(Sp) - a[8]);
                float ts  = a[1] + EPS_V;
                float px  = a[2] * inv, py = a[3] * inv;
                float tx  = a[4] / ts,  ty = a[5] / ts;
                float dx  = px - tx,    dy = py - ty;
                float coord = sqrtf(dx * dx + dy * dy);
                float conc  = 1.f - a[9];

                g_tile_contrib[tile] =
                    (a[6] + BG_W * a[7]) * (1.f / NTOT_F) +
                    (SPARSITY_W * ent + CONC_W * conc + COORD_W * coord) * (1.f / (float)NTILES);

                g_tile_cnt[tile] = 0;    // reset for next graph replay
                __threadfence();
                unsigned d = atomicAdd(&g_done, 1u);
                last = (d == NTILES - 1);
            }
            is_last = last;
        }
    }
    __syncthreads();

    if (is_last) {
        __threadfence();
        float v = 0.f;
        for (int i = tid; i < NTILES; i += 256)
            v += g_tile_contrib[i];
        #pragma unroll
        for (int o = 16; o; o >>= 1)
            v += __shfl_xor_sync(FULL, v, o);
        if (lane == 0) warp_red[wid][0] = v;
        __syncthreads();
        if (tid == 0) {
            float s = 0.f;
            #pragma unroll
            for (int w = 0; w < 8; w++) s += warp_red[w][0];
            out[0] = s;
            g_done = 0;   // reset for next graph replay
        }
    }
}

extern "C" void kernel_launch(void* const* d_in, const int* in_sizes, int n_in,
                              void* d_out, int out_size) {
    const float4* pred = (const float4*)d_in[0];
    const float4* tgt  = (const float4*)d_in[1];
    float* out = (float*)d_out;
    loss_kernel<<<NHALF, 256>>>(pred, tgt, out);
}

// round 6
// speedup vs baseline: 1.5378x; 1.5378x over previous
#include <cuda_runtime.h>
#include <math.h>

#define HW 4096
#define NTILES 640
#define NTOT_F 2621440.0f
#define EPS_V 1e-8f

#define SPARSITY_W 0.8f
#define CONC_W     1.5f
#define COORD_W    1.0f
#define BG_W       0.1f

__device__ float g_tile_contrib[NTILES];
__device__ unsigned int g_done = 0;

__device__ __forceinline__ float fast_tanh(float x) {
    float r;
    asm("tanh.approx.f32 %0, %1;" : "=f"(r) : "f"(x));
    return r;
}

// One CTA per tile, 256 threads, 16 px/thread. 51-reg cap -> 5 CTAs/SM ->
// all 640 CTAs resident in one wave (capacity 740).
__global__ __launch_bounds__(256, 5)
void loss_kernel(const float4* __restrict__ pred,
                 const float4* __restrict__ tgt,
                 float* __restrict__ out) {
    __shared__ float warp_red[8][10];
    __shared__ bool is_last;

    const int tile = blockIdx.x;
    const float4* __restrict__ P = pred + (size_t)tile * (HW / 4);
    const float4* __restrict__ T = tgt  + (size_t)tile * (HW / 4);

    const int tid  = threadIdx.x;
    const int lane = tid & 31;
    const int wid  = tid >> 5;

    // element j = 4*(tid + 256k) + c : col = ((4tid)&63)+c (k-invariant),
    //                                  row = (tid>>4) + 16k
    const float c0f = (float)((tid * 4) & 63);
    const float y0f = (float)(tid >> 4);

    float S = 0.f, Ts = 0.f;
    float wxp = 0.f, wyp = 0.f, wxt = 0.f, wyt = 0.f;
    float foc = 0.f, bg = 0.f, plog = 0.f, mxh = -0.5f;

    // depth-2 software pipeline over the 4 (pred,tgt) float4 pairs
    float4 xc = P[tid];
    float4 tc = T[tid];

    #pragma unroll
    for (int k = 0; k < 4; k++) {
        float4 xn, tn;
        if (k < 3) { xn = P[tid + 256 * (k + 1)]; tn = T[tid + 256 * (k + 1)]; }

        float xv[4] = {xc.x, xc.y, xc.z, xc.w};
        float tv[4] = {tc.x, tc.y, tc.z, tc.w};
        float pv[4];
        #pragma unroll
        for (int c = 0; c < 4; c++) {
            float x = xv[c];
            float t = tv[c];
            float h  = 0.5f * fast_tanh(0.5f * x);   // p - 0.5
            float p  = h + 0.5f;
            pv[c] = p;
            float pm = 0.5f + fabsf(h);              // sigmoid(|x|)
            float lp = __logf(pm);                   // -lp = log1p(e^{-|x|})
            float bce = fmaf(-x, t, fmaxf(x, 0.f) - lp);
            float om  = fabsf(t - p);                // 1 - p_t  (t in {0,1})
            float om2 = om * om;
            foc  = fmaf(om2, bce, foc);
            bg   = fmaf(om2, 1.f - t, bg);           // p^2 when t==0
            plog = fmaf(p, fminf(x, 0.f) + lp, plog);
            mxh  = fmaxf(mxh, h);
        }
        const float kf = (float)k;
        float gs = (pv[0] + pv[1]) + (pv[2] + pv[3]);
        float gw = fmaf(3.f, pv[3], fmaf(2.f, pv[2], pv[1]));
        S   += gs;
        wxp += gw;
        wyp  = fmaf(kf, gs, wyp);
        float gt = (tv[0] + tv[1]) + (tv[2] + tv[3]);
        float gu = fmaf(3.f, tv[3], fmaf(2.f, tv[2], tv[1]));
        Ts  += gt;
        wxt += gu;
        wyt  = fmaf(kf, gt, wyt);

        xc = xn; tc = tn;
    }

    float pxs = fmaf(c0f, S,  wxp);
    float pys = fmaf(y0f, S,  16.f * wyp);
    float txs = fmaf(c0f, Ts, wxt);
    float tys = fmaf(y0f, Ts, 16.f * wyt);
    float mx  = mxh + 0.5f;

    // warp butterfly: 9 sums + 1 max
    const unsigned FULL = 0xffffffffu;
    #pragma unroll
    for (int o = 16; o; o >>= 1) {
        S    += __shfl_xor_sync(FULL, S,    o);
        Ts   += __shfl_xor_sync(FULL, Ts,   o);
        pxs  += __shfl_xor_sync(FULL, pxs,  o);
        pys  += __shfl_xor_sync(FULL, pys,  o);
        txs  += __shfl_xor_sync(FULL, txs,  o);
        tys  += __shfl_xor_sync(FULL, tys,  o);
        foc  += __shfl_xor_sync(FULL, foc,  o);
        bg   += __shfl_xor_sync(FULL, bg,   o);
        plog += __shfl_xor_sync(FULL, plog, o);
        mx    = fmaxf(mx, __shfl_xor_sync(FULL, mx, o));
    }
    if (lane == 0) {
        warp_red[wid][0] = S;    warp_red[wid][1] = Ts;
        warp_red[wid][2] = pxs;  warp_red[wid][3] = pys;
        warp_red[wid][4] = txs;  warp_red[wid][5] = tys;
        warp_red[wid][6] = foc;  warp_red[wid][7] = bg;
        warp_red[wid][8] = plog; warp_red[wid][9] = mx;
    }
    __syncthreads();

    // cross-warp combine: 8 lanes of warp 0
    if (wid == 0 && lane < 8) {
        float a[10];
        #pragma unroll
        for (int i = 0; i < 10; i++) a[i] = warp_red[lane][i];
        const unsigned M8 = 0x000000ffu;
        #pragma unroll
        for (int o = 4; o; o >>= 1) {
            #pragma unroll
            for (int i = 0; i < 9; i++) a[i] += __shfl_xor_sync(M8, a[i], o);
            a[9] = fmaxf(a[9], __shfl_xor_sync(M8, a[9], o));
        }
        if (lane == 0) {
            float Sp  = a[0] + EPS_V;
            float inv = 1.f / Sp;
            float ent = inv * (a[0] * logf(Sp) - a[8]);
            float ts  = a[1] + EPS_V;
            float px  = a[2] * inv, py = a[3] * inv;
            float tx  = a[4] / ts,  ty = a[5] / ts;
            float dx  = px - tx,    dy = py - ty;
            float coord = sqrtf(dx * dx + dy * dy);
            float conc  = 1.f - a[9];

            g_tile_contrib[tile] =
                (a[6] + BG_W * a[7]) * (1.f / NTOT_F) +
                (SPARSITY_W * ent + CONC_W * conc + COORD_W * coord) * (1.f / (float)NTILES);

            __threadfence();
            unsigned r = atomicAdd(&g_done, 1u);
            is_last = (r == NTILES - 1);
        }
    }
    __syncthreads();

    if (is_last) {
        __threadfence();
        float v = 0.f;
        for (int i = tid; i < NTILES; i += 256)
            v += g_tile_contrib[i];
        #pragma unroll
        for (int o = 16; o; o >>= 1)
            v += __shfl_xor_sync(FULL, v, o);
        if (lane == 0) warp_red[wid][0] = v;
        __syncthreads();
        if (tid == 0) {
            float s = 0.f;
            #pragma unroll
            for (int w = 0; w < 8; w++) s += warp_red[w][0];
            out[0] = s;
            g_done = 0;   // reset for next graph replay
        }
    }
}

extern "C" void kernel_launch(void* const* d_in, const int* in_sizes, int n_in,
                              void* d_out, int out_size) {
    const float4* pred = (const float4*)d_in[0];
    const float4* tgt  = (const float4*)d_in[1];
    float* out = (float*)d_out;
    loss_kernel<<<NTILES, 256>>>(pred, tgt, out);
}